// round 8
// baseline (speedup 1.0000x reference)
#include <cuda_runtime.h>
#include <cstdint>

// out[e, 0:128] = node_states[src[e], :]; out[e, 128:256] = node_states[tgt[e], :]
// Persistent grid-stride variant of the R3 winner (49.6us): 1184 CTAs
// (148 SMs x 8) loop over edge pairs instead of 20000 one-shot CTAs.
// Eliminates CTA dispatch/drain churn; scoreboard overlaps loads across
// loop iterations for >4 effective MLP. All other knobs are the proven
// config: 2 edges/warp-iter, int2 index loads, __ldg gathers, __stcs stores.
// Binder: 328 MB DRAM write stream (~6.6 TB/s effective, 83% of spec).

__global__ __launch_bounds__(256) void node_propagate_persist(
    const float4* __restrict__ ns,   // [N_NODES, 32] as float4
    const int* __restrict__ src,     // [E] int32
    const int* __restrict__ tgt,     // [E] int32
    float4* __restrict__ out,        // [E, 64] as float4
    int nPairs)                      // E/2
{
    const int lane    = threadIdx.x & 31;
    const int warp0   = (int)((blockIdx.x * (unsigned)blockDim.x + threadIdx.x) >> 5);
    const int nWarps  = (int)((gridDim.x * (unsigned)blockDim.x) >> 5);

    for (int p = warp0; p < nPairs; p += nWarps) {
        const int e0 = p * 2;

        // Adjacent int32 indices -> one 8B broadcast load each.
        const int2 s2 = *(const int2*)(src + e0);
        const int2 t2 = *(const int2*)(tgt + e0);

        // 4 independent gathers (node_states is 5.12 MB, L2-resident);
        // successive loop iterations overlap via scoreboard.
        const float4 a0 = __ldg(&ns[(size_t)s2.x * 32 + lane]);
        const float4 b0 = __ldg(&ns[(size_t)t2.x * 32 + lane]);
        const float4 a1 = __ldg(&ns[(size_t)s2.y * 32 + lane]);
        const float4 b1 = __ldg(&ns[(size_t)t2.y * 32 + lane]);

        // Evict-first stores: full-line evictions, protect L2 gather set.
        float4* o = out + (size_t)e0 * 64;
        __stcs(o +      lane, a0);
        __stcs(o + 32 + lane, b0);
        __stcs(o + 64 + lane, a1);
        __stcs(o + 96 + lane, b1);
    }
}

// Tail for odd E (not used for E=320000).
__global__ void node_propagate_tail(
    const float4* __restrict__ ns,
    const int* __restrict__ src,
    const int* __restrict__ tgt,
    float4* __restrict__ out,
    int e)
{
    const int lane = threadIdx.x & 31;
    const int s = __ldg(&src[e]);
    const int t = __ldg(&tgt[e]);
    const float4 a = __ldg(&ns[(size_t)s * 32 + lane]);
    const float4 b = __ldg(&ns[(size_t)t * 32 + lane]);
    float4* o = out + (size_t)e * 64;
    __stcs(o + lane,      a);
    __stcs(o + 32 + lane, b);
}

extern "C" void kernel_launch(void* const* d_in, const int* in_sizes, int n_in,
                              void* d_out, int out_size)
{
    const float4* ns  = (const float4*)d_in[0];
    const int*    src = (const int*)d_in[1];
    const int*    tgt = (const int*)d_in[2];
    float4*       out = (float4*)d_out;

    const int E      = in_sizes[1];   // 320000
    const int nPairs = E / 2;

    // 148 SMs x 8 resident CTAs of 256 threads (occupancy-limited ~8/SM).
    const int blocks  = 148 * 8;
    const int threads = 256;

    node_propagate_persist<<<blocks, threads>>>(ns, src, tgt, out, nPairs);

    if (E & 1)
        node_propagate_tail<<<1, 32>>>(ns, src, tgt, out, E - 1);
}

// round 9
// speedup vs baseline: 1.0173x; 1.0173x over previous
#include <cuda_runtime.h>
#include <cstdint>

// out[e, 0:128] = node_states[src[e], :]; out[e, 128:256] = node_states[tgt[e], :]
// 256-bit access variant (sm_100+ ld/st .v8.b32): lane l moves 32B; lanes 0-15
// carry the source row half, lanes 16-31 the target half -> one LDG.256 + one
// STG.256 per edge per warp (2 edges/warp => 2+2 memory instructions vs 4+4
// 128-bit in the R3 winner). Same bytes, half the L1tex wavefront issue slots.
// Binder: 328 MB DRAM write stream; L1tex top-ranked (73-80%) in all profiles.

__global__ __launch_bounds__(256) void node_propagate_v8(
    const float* __restrict__ ns,    // [N_NODES, 128] floats (512B rows)
    const int* __restrict__ src,     // [E] int32
    const int* __restrict__ tgt,     // [E] int32
    float* __restrict__ out,         // [E, 256] floats (1KB rows)
    int nPairs)                      // E/2
{
    const int gwarp = (int)((blockIdx.x * (unsigned)blockDim.x + threadIdx.x) >> 5);
    const int lane  = threadIdx.x & 31;
    if (gwarp >= nPairs) return;
    const int e0 = gwarp * 2;

    // Broadcast index pairs (8B each).
    const int2 s2 = *(const int2*)(src + e0);
    const int2 t2 = *(const int2*)(tgt + e0);

    // Lane roles: lanes 0-15 -> source row, lanes 16-31 -> target row.
    const bool hi   = lane >= 16;
    const int  sub  = lane & 15;              // 16 lanes x 8 floats = 128 floats
    const int  r0   = hi ? t2.x : s2.x;
    const int  r1   = hi ? t2.y : s2.y;

    const float* in0 = ns + (size_t)r0 * 128 + sub * 8;
    const float* in1 = ns + (size_t)r1 * 128 + sub * 8;
    float*       o0  = out + (size_t)e0 * 256 + lane * 8;
    float*       o1  = o0 + 256;

    unsigned a0,a1,a2,a3,a4,a5,a6,a7;
    unsigned b0,b1,b2,b3,b4,b5,b6,b7;

    // Two independent 256-bit gathers in flight (node_states L2-resident).
    asm volatile("ld.global.nc.v8.b32 {%0,%1,%2,%3,%4,%5,%6,%7}, [%8];"
        : "=r"(a0),"=r"(a1),"=r"(a2),"=r"(a3),
          "=r"(a4),"=r"(a5),"=r"(a6),"=r"(a7)
        : "l"(in0));
    asm volatile("ld.global.nc.v8.b32 {%0,%1,%2,%3,%4,%5,%6,%7}, [%8];"
        : "=r"(b0),"=r"(b1),"=r"(b2),"=r"(b3),
          "=r"(b4),"=r"(b5),"=r"(b6),"=r"(b7)
        : "l"(in1));

    // 256-bit streaming stores: one full 1KB output row per warp instruction.
    asm volatile("st.global.cs.v8.b32 [%0], {%1,%2,%3,%4,%5,%6,%7,%8};"
        :: "l"(o0),
           "r"(a0),"r"(a1),"r"(a2),"r"(a3),
           "r"(a4),"r"(a5),"r"(a6),"r"(a7) : "memory");
    asm volatile("st.global.cs.v8.b32 [%0], {%1,%2,%3,%4,%5,%6,%7,%8};"
        :: "l"(o1),
           "r"(b0),"r"(b1),"r"(b2),"r"(b3),
           "r"(b4),"r"(b5),"r"(b6),"r"(b7) : "memory");
}

// Tail for odd E (unused for E=320000).
__global__ void node_propagate_tail(
    const float4* __restrict__ ns,
    const int* __restrict__ src,
    const int* __restrict__ tgt,
    float4* __restrict__ out,
    int e)
{
    const int lane = threadIdx.x & 31;
    const int s = __ldg(&src[e]);
    const int t = __ldg(&tgt[e]);
    const float4 a = __ldg(&ns[(size_t)s * 32 + lane]);
    const float4 b = __ldg(&ns[(size_t)t * 32 + lane]);
    float4* o = out + (size_t)e * 64;
    __stcs(o + lane,      a);
    __stcs(o + 32 + lane, b);
}

extern "C" void kernel_launch(void* const* d_in, const int* in_sizes, int n_in,
                              void* d_out, int out_size)
{
    const float* ns  = (const float*)d_in[0];
    const int*   src = (const int*)d_in[1];
    const int*   tgt = (const int*)d_in[2];
    float*       out = (float*)d_out;

    const int E      = in_sizes[1];   // 320000
    const int nPairs = E / 2;

    const int threads = 256;          // 8 warps -> 16 edges per block
    const int blocks  = (nPairs * 32 + threads - 1) / threads;

    node_propagate_v8<<<blocks, threads>>>(ns, src, tgt, out, nPairs);

    if (E & 1)
        node_propagate_tail<<<1, 32>>>((const float4*)ns, src, tgt,
                                       (float4*)out, E - 1);
}